// round 2
// baseline (speedup 1.0000x reference)
#include <cuda_runtime.h>

// ---------------------------------------------------------------------------
// Block-sparse linear: y = x @ W^T + bias, W assembled from K dense 64x64 tiles.
// Strategy: CSR-bucket tiles by output block-row (deterministic), then a
// tf32 mma.sync GEMM per (n-tile x out-block-row) CTA.
// ---------------------------------------------------------------------------

#define TM 128          // rows of x per CTA
#define BSZ 64          // block size
#define NTHREADS 256

// CSR scratch in device globals (no allocations allowed).
__device__ int g_start[257];
__device__ int g_list[16384];

// Deterministic CSR build: bucket tile index k by row_idx[k], order by k.
__global__ void build_csr_kernel(const int* __restrict__ row_idx, int K, int nrows) {
    __shared__ int s_row[8192];
    __shared__ int s_cnt[256];
    int tid = threadIdx.x;
    for (int i = tid; i < K; i += blockDim.x) s_row[i] = row_idx[i];
    for (int i = tid; i < nrows; i += blockDim.x) s_cnt[i] = 0;
    __syncthreads();
    for (int i = tid; i < K; i += blockDim.x) atomicAdd(&s_cnt[s_row[i]], 1);
    __syncthreads();
    if (tid == 0) {
        int acc = 0;
        for (int r = 0; r < nrows; r++) { g_start[r] = acc; acc += s_cnt[r]; }
        g_start[nrows] = acc;
    }
    __syncthreads();
    // rank of k within its row = #{j < k : row[j] == row[k]}  (deterministic)
    for (int k = tid; k < K; k += blockDim.x) {
        int r = s_row[k];
        int rank = 0;
        for (int j = 0; j < k; j++) rank += (s_row[j] == r) ? 1 : 0;
        g_list[g_start[r] + rank] = k;
    }
}

__device__ __forceinline__ unsigned int f2tf(float f) {
    unsigned int r;
    asm("cvt.rna.tf32.f32 %0, %1;" : "=r"(r) : "f"(f));
    return r;
}

__device__ __forceinline__ void mma_tf32(float* c, const unsigned int* a,
                                         unsigned int b0, unsigned int b1) {
    asm volatile(
        "mma.sync.aligned.m16n8k8.row.col.f32.tf32.tf32.f32 "
        "{%0,%1,%2,%3}, {%4,%5,%6,%7}, {%8,%9}, {%0,%1,%2,%3};\n"
        : "+f"(c[0]), "+f"(c[1]), "+f"(c[2]), "+f"(c[3])
        : "r"(a[0]), "r"(a[1]), "r"(a[2]), "r"(a[3]), "r"(b0), "r"(b1));
}

// XOR swizzle for a [rows x 64] f32 tile: conflict-free mma-fragment reads.
#define SWZ(row, col) (((row) << 6) + ((col) ^ (((row) & 7) << 2)))

__global__ void __launch_bounds__(NTHREADS)
bsl_kernel(const float* __restrict__ x, const float* __restrict__ blocks,
           const float* __restrict__ bias, const int* __restrict__ col_idx,
           float* __restrict__ y, int IN, int OUT) {
    // 48KB static smem exactly
    __shared__ unsigned int xs[TM * BSZ];    // 32KB, swizzled tf32 x tile
    __shared__ unsigned int bsm[BSZ * BSZ];  // 16KB, swizzled tf32 block [o][i]

    const int tid  = threadIdx.x;
    const int lane = tid & 31;
    const int warp = tid >> 5;
    const int wm   = warp & 3;   // 4 warps along M (32 rows each)
    const int wn   = warp >> 2;  // 2 warps along N (32 cols each)
    const int g    = lane >> 2;  // groupID
    const int t    = lane & 3;   // thread-in-group

    const int n0   = blockIdx.x * TM;
    const int rblk = blockIdx.y;
    const int out0 = rblk * BSZ;

    float acc[2][4][4];
#pragma unroll
    for (int mf = 0; mf < 2; mf++)
#pragma unroll
        for (int nf = 0; nf < 4; nf++)
#pragma unroll
            for (int i = 0; i < 4; i++) acc[mf][nf][i] = 0.0f;

    const int beg = g_start[rblk];
    const int end = g_start[rblk + 1];

    for (int idx = beg; idx < end; idx++) {
        const int k  = g_list[idx];
        const int c0 = col_idx[k] * BSZ;

        // ---- load x tile [128 x 64] (float4, swizzled, tf32-rounded) ----
#pragma unroll
        for (int i = 0; i < 8; i++) {
            int lin = tid + i * NTHREADS;
            int row = lin >> 4;       // 16 float4 per row
            int q   = lin & 15;
            float4 v = *reinterpret_cast<const float4*>(
                x + (size_t)(n0 + row) * IN + c0 + q * 4);
            unsigned int* dst = xs + SWZ(row, q * 4);
            dst[0] = f2tf(v.x); dst[1] = f2tf(v.y);
            dst[2] = f2tf(v.z); dst[3] = f2tf(v.w);
        }
        // ---- load block tile [64 x 64], layout [o][i] ----
#pragma unroll
        for (int i = 0; i < 4; i++) {
            int lin = tid + i * NTHREADS;
            int row = lin >> 4;
            int q   = lin & 15;
            float4 v = *reinterpret_cast<const float4*>(
                blocks + (size_t)k * (BSZ * BSZ) + row * BSZ + q * 4);
            unsigned int* dst = bsm + SWZ(row, q * 4);
            dst[0] = f2tf(v.x); dst[1] = f2tf(v.y);
            dst[2] = f2tf(v.z); dst[3] = f2tf(v.w);
        }
        __syncthreads();

        // ---- mma: D[m128,n64] += X[m128,k64] * B^T  (B row o, col i) ----
#pragma unroll
        for (int kk = 0; kk < BSZ; kk += 8) {
            unsigned int a[2][4];
#pragma unroll
            for (int mf = 0; mf < 2; mf++) {
                int r = wm * 32 + mf * 16 + g;
                a[mf][0] = xs[SWZ(r,     kk + t)];
                a[mf][1] = xs[SWZ(r + 8, kk + t)];
                a[mf][2] = xs[SWZ(r,     kk + 4 + t)];
                a[mf][3] = xs[SWZ(r + 8, kk + 4 + t)];
            }
#pragma unroll
            for (int nf = 0; nf < 4; nf++) {
                int o = wn * 32 + nf * 8 + g;
                unsigned int b0 = bsm[SWZ(o, kk + t)];
                unsigned int b1 = bsm[SWZ(o, kk + 4 + t)];
#pragma unroll
                for (int mf = 0; mf < 2; mf++)
                    mma_tf32(acc[mf][nf], a[mf], b0, b1);
            }
        }
        __syncthreads();
    }

    // ---- epilogue: y = acc + bias ----
#pragma unroll
    for (int mf = 0; mf < 2; mf++) {
#pragma unroll
        for (int nf = 0; nf < 4; nf++) {
            int row = n0 + wm * 32 + mf * 16 + g;
            int col = out0 + wn * 32 + nf * 8 + 2 * t;
            float2 bv = *reinterpret_cast<const float2*>(bias + col);
            float2 lo, hi;
            lo.x = acc[mf][nf][0] + bv.x;
            lo.y = acc[mf][nf][1] + bv.y;
            hi.x = acc[mf][nf][2] + bv.x;
            hi.y = acc[mf][nf][3] + bv.y;
            *reinterpret_cast<float2*>(y + (size_t)row * OUT + col) = lo;
            *reinterpret_cast<float2*>(y + (size_t)(row + 8) * OUT + col) = hi;
        }
    }
}

extern "C" void kernel_launch(void* const* d_in, const int* in_sizes, int n_in,
                              void* d_out, int out_size) {
    const float* x      = (const float*)d_in[0];
    const float* blocks = (const float*)d_in[1];
    const float* bias   = (const float*)d_in[2];
    const int*   row_i  = (const int*)d_in[3];
    const int*   col_i  = (const int*)d_in[4];
    float*       y      = (float*)d_out;

    const int K   = in_sizes[3];
    const int OUT = in_sizes[2];
    const int IN  = 4096;                 // problem shape (x is [N, 4096])
    const int N   = in_sizes[0] / IN;
    const int nrows = OUT / BSZ;

    build_csr_kernel<<<1, 1024>>>(row_i, K, nrows);

    dim3 grid(N / TM, nrows);
    bsl_kernel<<<grid, NTHREADS>>>(x, blocks, bias, col_i, y, IN, OUT);
}